// round 1
// baseline (speedup 1.0000x reference)
#include <cuda_runtime.h>
#include <math.h>

#define BATCH 64
#define CIN   64
#define NNODE 4097
#define TNODE 4096
#define HID   128
#define LAT   64
#define EPSV  1e-5f

#define K1CNT 192
#define K2CNT 384
#define NT1   64
#define NT2   16
#define THR1  512
#define THR2  256
#define GRID1 304
#define GRID2 304

// -------- scratch (device globals; no allocation allowed) ----------
__device__ float   g_featsT[2][(size_t)BATCH * NNODE * CIN];   // (B,N,C) transposed feats
__device__ float   g_out1  [2][(size_t)BATCH * NNODE * HID];   // conv1 raw output (node0 = 0)
__device__ float   g_stats1[2][BATCH][2];                      // sum, sumsq of conv1 raw
__device__ float   g_stats2[2][BATCH][2];                      // sum, sumsq of conv2 raw
__device__ unsigned g_max2 [2][BATCH][HID];                    // per (b,o) max of conv2 raw (order-encoded)

// monotone float<->uint encoding so atomicMax(unsigned) == float max
__device__ __forceinline__ unsigned f2ord(float f) {
    unsigned u = __float_as_uint(f);
    return (u & 0x80000000u) ? ~u : (u | 0x80000000u);
}
__device__ __forceinline__ float ord2f(unsigned u) {
    return __uint_as_float((u & 0x80000000u) ? (u ^ 0x80000000u) : ~u);
}

// ---------------- init: zero stats, node-0 rows, max buffers ----------------
__global__ void init_kernel() {
    int i = blockIdx.x * blockDim.x + threadIdx.x;
    if (i < 2 * BATCH * HID) {
        int e = i / (BATCH * HID);
        int r = i % (BATCH * HID);
        int b = r / HID, o = r % HID;
        g_max2[e][b][o] = 0x80000000u;                        // encodes 0.0f (null node contributes 0)
        g_out1[e][(size_t)b * NNODE * HID + o] = 0.0f;        // zero null-node row
    }
    if (i < 2 * BATCH) {
        int e = i / BATCH, b = i % BATCH;
        g_stats1[e][b][0] = 0.f; g_stats1[e][b][1] = 0.f;
        g_stats2[e][b][0] = 0.f; g_stats2[e][b][1] = 0.f;
    }
}

// ---------------- transpose (B,C,N) -> (B,N,C) for both feature tensors -------------
__global__ void transpose_kernel(const float* __restrict__ lf, const float* __restrict__ pf) {
    __shared__ float tile[32][33];
    int e = blockIdx.z >> 6;
    int b = blockIdx.z & 63;
    const float* src = e ? pf : lf;
    int n0 = blockIdx.x << 5, c0 = blockIdx.y << 5;
    int tx = threadIdx.x, ty = threadIdx.y;
#pragma unroll
    for (int i = 0; i < 32; i += 8) {
        int n = n0 + tx;
        if (n < NNODE) tile[ty + i][tx] = src[((size_t)b * CIN + c0 + ty + i) * NNODE + n];
    }
    __syncthreads();
#pragma unroll
    for (int i = 0; i < 32; i += 8) {
        int n = n0 + ty + i;
        if (n < NNODE) g_featsT[e][((size_t)b * NNODE + n) * CIN + c0 + tx] = tile[tx][ty + i];
    }
}

// FMA macro for conv1 (4 nodes x 4 outputs per thread)
#define STEP1(COMP, JJ) { \
    float4 wv = *(const float4*)&s_W[(j + JJ) * HID + o4]; \
    acc[0][0] += ga.COMP * wv.x; acc[0][1] += ga.COMP * wv.y; acc[0][2] += ga.COMP * wv.z; acc[0][3] += ga.COMP * wv.w; \
    acc[1][0] += gb.COMP * wv.x; acc[1][1] += gb.COMP * wv.y; acc[1][2] += gb.COMP * wv.z; acc[1][3] += gb.COMP * wv.w; \
    acc[2][0] += gc.COMP * wv.x; acc[2][1] += gc.COMP * wv.y; acc[2][2] += gc.COMP * wv.z; acc[2][3] += gc.COMP * wv.w; \
    acc[3][0] += gd.COMP * wv.x; acc[3][1] += gd.COMP * wv.y; acc[3][2] += gd.COMP * wv.z; acc[3][3] += gd.COMP * wv.w; }

// FMA macro for conv2 (2 nodes x 4 outputs per thread)
#define STEP2(COMP, JJ) { \
    float4 wv = *(const float4*)&s_W[(j + JJ) * HID + o4]; \
    acc[0][0] += ga.COMP * wv.x; acc[0][1] += ga.COMP * wv.y; acc[0][2] += ga.COMP * wv.z; acc[0][3] += ga.COMP * wv.w; \
    acc[1][0] += gb.COMP * wv.x; acc[1][1] += gb.COMP * wv.y; acc[1][2] += gb.COMP * wv.z; acc[1][3] += gb.COMP * wv.w; }

// ---------------- conv1: gather(featsT) -> GEMM(K=192) -> store raw + stats --------
__global__ void __launch_bounds__(THR1, 1) conv1_kernel(
    const int* __restrict__ children,
    const float* __restrict__ Wl, const float* __restrict__ bl,
    const float* __restrict__ Wp, const float* __restrict__ bp)
{
    extern __shared__ float smem[];
    float* s_W   = smem;                    // 192*128 = 24576 floats
    float* s_g   = smem + 24576;            // 64*192  = 12288
    float* s_b   = smem + 36864;            // 128
    float* s_red = smem + 36992;            // 32
    int*   s_ch  = (int*)(smem + 37024);    // 192

    const int tid = threadIdx.x;
    const int totalW = 2 * BATCH * (TNODE / NT1);       // 8192
    const int chunk = (totalW + GRID1 - 1) / GRID1;
    int wstart = blockIdx.x * chunk;
    int wend = min(totalW, wstart + chunk);
    int lastE = -1;

    const int tx = tid & 31, ty = tid >> 5;
    const int o4 = tx << 2;
    const int nb = ty << 2;

    for (int w = wstart; w < wend; ++w) {
        int e = w >> 12;
        int r = w & 4095;
        int b = r >> 6;
        int tl = r & 63;
        int n0 = 1 + tl * NT1;

        __syncthreads();   // previous tile's compute done before smem overwrite
        if (e != lastE) {
            const float* Wg = e ? Wp : Wl;
            const float* bg = e ? bp : bl;
            for (int idx = tid; idx < K1CNT * HID; idx += THR1) {
                int j = idx >> 7, o = idx & 127;
                s_W[idx] = Wg[o * K1CNT + (j & 63) * 3 + (j >> 6)];   // j = k*64 + c
            }
            if (tid < HID) s_b[tid] = bg[tid];
            lastE = e;
        }
        if (tid < 3 * NT1) s_ch[tid] = children[b * 3 * TNODE + 3 * (n0 - 1) + tid];
        __syncthreads();

        // gather: 3*NT1 child vectors of CIN floats each (contiguous 256B)
        for (int idx = tid; idx < NT1 * 3 * (CIN / 4); idx += THR1) {
            int q = idx & 15, v = idx >> 4;
            int k = v % 3, i = v / 3;
            int child = s_ch[i * 3 + k];
            float4 val = *(const float4*)&g_featsT[e][((size_t)b * NNODE + child) * CIN + (q << 2)];
            *(float4*)&s_g[i * K1CNT + k * CIN + (q << 2)] = val;
        }
        __syncthreads();

        float acc[4][4];
        {
            float b0 = s_b[o4], b1 = s_b[o4 + 1], b2 = s_b[o4 + 2], b3 = s_b[o4 + 3];
#pragma unroll
            for (int i = 0; i < 4; ++i) { acc[i][0] = b0; acc[i][1] = b1; acc[i][2] = b2; acc[i][3] = b3; }
        }
        const float* g0 = s_g + (nb + 0) * K1CNT;
        const float* g1 = s_g + (nb + 1) * K1CNT;
        const float* g2 = s_g + (nb + 2) * K1CNT;
        const float* g3 = s_g + (nb + 3) * K1CNT;

#pragma unroll 4
        for (int j = 0; j < K1CNT; j += 4) {
            float4 ga = *(const float4*)(g0 + j);
            float4 gb = *(const float4*)(g1 + j);
            float4 gc = *(const float4*)(g2 + j);
            float4 gd = *(const float4*)(g3 + j);
            STEP1(x, 0) STEP1(y, 1) STEP1(z, 2) STEP1(w, 3)
        }

        float ls = 0.f, lss = 0.f;
#pragma unroll
        for (int i = 0; i < 4; ++i) {
            int n = n0 + nb + i;
            float4 ov = make_float4(acc[i][0], acc[i][1], acc[i][2], acc[i][3]);
            *(float4*)&g_out1[e][((size_t)b * NNODE + n) * HID + o4] = ov;
            ls  += acc[i][0] + acc[i][1] + acc[i][2] + acc[i][3];
            lss += acc[i][0] * acc[i][0] + acc[i][1] * acc[i][1]
                 + acc[i][2] * acc[i][2] + acc[i][3] * acc[i][3];
        }
#pragma unroll
        for (int off = 16; off > 0; off >>= 1) {
            ls  += __shfl_xor_sync(0xffffffffu, ls, off);
            lss += __shfl_xor_sync(0xffffffffu, lss, off);
        }
        if ((tid & 31) == 0) { s_red[ty] = ls; s_red[16 + ty] = lss; }
        __syncthreads();
        if (tid < 32) {
            float v1 = (tid < 16) ? s_red[tid] : 0.f;
            float v2 = (tid < 16) ? s_red[16 + tid] : 0.f;
#pragma unroll
            for (int off = 8; off > 0; off >>= 1) {
                v1 += __shfl_xor_sync(0xffffffffu, v1, off);
                v2 += __shfl_xor_sync(0xffffffffu, v2, off);
            }
            if (tid == 0) {
                atomicAdd(&g_stats1[e][b][0], v1);
                atomicAdd(&g_stats1[e][b][1], v2);
            }
        }
    }
}

// ---------------- conv2: gather(LN+relu(out1)) -> GEMM(K=384) -> stats + max --------
__global__ void __launch_bounds__(THR2, 1) conv2_kernel(
    const int* __restrict__ children,
    const float* __restrict__ Wl, const float* __restrict__ bl,
    const float* __restrict__ Wp, const float* __restrict__ bp)
{
    extern __shared__ float smem[];
    float*    s_W   = smem;                       // 384*128 = 49152 floats
    float*    s_g   = smem + 49152;               // 16*384  = 6144
    float*    s_b   = smem + 55296;               // 128
    float*    s_red = smem + 55424;               // 16
    unsigned* s_max = (unsigned*)(smem + 55440);  // 128
    int*      s_ch  = (int*)(smem + 55568);       // 48   -> total 55616 floats = 222464 B

    const int tid = threadIdx.x;
    const int totalW = 2 * BATCH * (TNODE / NT2);   // 32768
    const int chunk = (totalW + GRID2 - 1) / GRID2;
    int wstart = blockIdx.x * chunk;
    int wend = min(totalW, wstart + chunk);
    int lastE = -1;

    const int tx = tid & 31, ty = tid >> 5;
    const int o4 = tx << 2;
    const int nb = ty << 1;      // 2 nodes per thread

    for (int w = wstart; w < wend; ++w) {
        int e = w >> 14;
        int r = w & 16383;
        int b = r >> 8;
        int tl = r & 255;
        int n0 = 1 + tl * NT2;

        __syncthreads();
        if (e != lastE) {
            const float* Wg = e ? Wp : Wl;
            const float* bg = e ? bp : bl;
            for (int idx = tid; idx < K2CNT * HID; idx += THR2) {
                int j = idx >> 7, o = idx & 127;
                s_W[idx] = Wg[o * K2CNT + (j & 127) * 3 + (j >> 7)];  // j = k*128 + c
            }
            if (tid < HID) s_b[tid] = bg[tid];
            lastE = e;
        }
        if (tid < 3 * NT2) s_ch[tid] = children[b * 3 * TNODE + 3 * (n0 - 1) + tid];
        if (tid < HID) s_max[tid] = 0x80000000u;

        // LN1 stats for this example (atomics from conv1 kernel completed at launch boundary)
        float st  = g_stats1[e][b][0];
        float sst = g_stats1[e][b][1];
        const float cntv = (float)(HID * NNODE);
        float mean = st / cntv;
        float var  = (sst - st * st / cntv) / (cntv - 1.f);
        float inv  = 1.f / (sqrtf(var) + EPSV);
        __syncthreads();

        // gather 3*NT2 child vectors of HID floats, applying relu(LN(.)) on the fly
        for (int idx = tid; idx < NT2 * 3 * (HID / 4); idx += THR2) {
            int q = idx & 31, v = idx >> 5;
            int k = v % 3, i = v / 3;
            int child = s_ch[i * 3 + k];
            float4 t = *(const float4*)&g_out1[e][((size_t)b * NNODE + child) * HID + (q << 2)];
            t.x = fmaxf(0.f, (t.x - mean) * inv);
            t.y = fmaxf(0.f, (t.y - mean) * inv);
            t.z = fmaxf(0.f, (t.z - mean) * inv);
            t.w = fmaxf(0.f, (t.w - mean) * inv);
            *(float4*)&s_g[i * K2CNT + k * HID + (q << 2)] = t;
        }
        __syncthreads();

        float acc[2][4];
        {
            float b0 = s_b[o4], b1 = s_b[o4 + 1], b2 = s_b[o4 + 2], b3 = s_b[o4 + 3];
            acc[0][0] = b0; acc[0][1] = b1; acc[0][2] = b2; acc[0][3] = b3;
            acc[1][0] = b0; acc[1][1] = b1; acc[1][2] = b2; acc[1][3] = b3;
        }
        const float* g0 = s_g + (nb + 0) * K2CNT;
        const float* g1 = s_g + (nb + 1) * K2CNT;

#pragma unroll 4
        for (int j = 0; j < K2CNT; j += 4) {
            float4 ga = *(const float4*)(g0 + j);
            float4 gb = *(const float4*)(g1 + j);
            STEP2(x, 0) STEP2(y, 1) STEP2(z, 2) STEP2(w, 3)
        }

        // raw stats + per-o max (no store of conv2 output!)
        float ls = 0.f, lss = 0.f;
#pragma unroll
        for (int i = 0; i < 2; ++i) {
            ls  += acc[i][0] + acc[i][1] + acc[i][2] + acc[i][3];
            lss += acc[i][0] * acc[i][0] + acc[i][1] * acc[i][1]
                 + acc[i][2] * acc[i][2] + acc[i][3] * acc[i][3];
        }
#pragma unroll
        for (int q = 0; q < 4; ++q) {
            float m = fmaxf(acc[0][q], acc[1][q]);
            atomicMax(&s_max[o4 + q], f2ord(m));
        }
#pragma unroll
        for (int off = 16; off > 0; off >>= 1) {
            ls  += __shfl_xor_sync(0xffffffffu, ls, off);
            lss += __shfl_xor_sync(0xffffffffu, lss, off);
        }
        if ((tid & 31) == 0) { s_red[ty] = ls; s_red[8 + ty] = lss; }
        __syncthreads();
        if (tid < 32) {
            float v1 = (tid < 8) ? s_red[tid] : 0.f;
            float v2 = (tid < 8) ? s_red[8 + tid] : 0.f;
#pragma unroll
            for (int off = 4; off > 0; off >>= 1) {
                v1 += __shfl_xor_sync(0xffffffffu, v1, off);
                v2 += __shfl_xor_sync(0xffffffffu, v2, off);
            }
            if (tid == 0) {
                atomicAdd(&g_stats2[e][b][0], v1);
                atomicAdd(&g_stats2[e][b][1], v2);
            }
        }
        if (tid < HID) atomicMax(&g_max2[e][b][tid], s_max[tid]);
    }
}

// ---------------- finalize: LN2+relu on max, concat, mu/logvar GEMVs ---------------
__global__ void finalize_kernel(const float* __restrict__ Wmu, const float* __restrict__ bmu,
                                const float* __restrict__ Wlv, const float* __restrict__ blv,
                                float* __restrict__ out)
{
    __shared__ float comb[2 * HID];
    int b = blockIdx.x, tid = threadIdx.x;
    const float cntv = (float)(HID * NNODE);
#pragma unroll
    for (int e = 0; e < 2; ++e) {
        float st  = g_stats2[e][b][0];
        float sst = g_stats2[e][b][1];
        float mean = st / cntv;
        float var  = (sst - st * st / cntv) / (cntv - 1.f);
        float inv  = 1.f / (sqrtf(var) + EPSV);
        if (tid < HID) {
            float m = ord2f(g_max2[e][b][tid]);
            comb[e * HID + tid] = fmaxf(0.f, (m - mean) * inv);
        }
    }
    __syncthreads();
    if (tid < 64) {
        float acc = bmu[tid];
        for (int j = 0; j < 2 * HID; ++j) acc += Wmu[tid * 2 * HID + j] * comb[j];
        out[b * LAT + tid] = acc;
    } else if (tid < 128) {
        int t = tid - 64;
        float acc = blv[t];
        for (int j = 0; j < 2 * HID; ++j) acc += Wlv[t * 2 * HID + j] * comb[j];
        out[BATCH * LAT + b * LAT + t] = acc;
    }
}

// -------------------------------- launch --------------------------------
extern "C" void kernel_launch(void* const* d_in, const int* in_sizes, int n_in,
                              void* d_out, int out_size)
{
    const float* lf  = (const float*)d_in[0];
    const float* pf  = (const float*)d_in[1];
    const int*   ch  = (const int*)d_in[2];
    const float* Wl1 = (const float*)d_in[3];  const float* bl1 = (const float*)d_in[4];
    const float* Wl2 = (const float*)d_in[5];  const float* bl2 = (const float*)d_in[6];
    const float* Wp1 = (const float*)d_in[7];  const float* bp1 = (const float*)d_in[8];
    const float* Wp2 = (const float*)d_in[9];  const float* bp2 = (const float*)d_in[10];
    const float* Wmu = (const float*)d_in[11]; const float* bmu = (const float*)d_in[12];
    const float* Wlv = (const float*)d_in[13]; const float* blv = (const float*)d_in[14];
    float* out = (float*)d_out;

    const int SMEM1 = 37216 * 4;   // 148,864 B
    const int SMEM2 = 55616 * 4;   // 222,464 B
    cudaFuncSetAttribute(conv1_kernel, cudaFuncAttributeMaxDynamicSharedMemorySize, SMEM1);
    cudaFuncSetAttribute(conv2_kernel, cudaFuncAttributeMaxDynamicSharedMemorySize, SMEM2);

    init_kernel<<<(2 * BATCH * HID + 255) / 256, 256>>>();
    transpose_kernel<<<dim3((NNODE + 31) / 32, CIN / 32, 2 * BATCH), dim3(32, 8)>>>(lf, pf);
    conv1_kernel<<<GRID1, THR1, SMEM1>>>(ch, Wl1, bl1, Wp1, bp1);
    conv2_kernel<<<GRID2, THR2, SMEM2>>>(ch, Wl2, bl2, Wp2, bp2);
    finalize_kernel<<<BATCH, 128>>>(Wmu, bmu, Wlv, blv, out);
}

// round 6
// speedup vs baseline: 2.9828x; 2.9828x over previous
#include <cuda_runtime.h>
#include <math.h>
#include <stdint.h>

#define BATCH 64
#define CIN   64
#define NNODE 4097
#define TNODE 4096
#define HID   128
#define LAT   64
#define EPSV  1e-5f

// -------- scratch (device globals; no allocation allowed) ----------
__device__ float    g_featsT[2][(size_t)BATCH * NNODE * CIN];   // (B,N,C), tf32-rounded
__device__ float    g_out1  [2][(size_t)BATCH * NNODE * HID];   // conv1 raw output (node0 row = 0)
__device__ float    g_h     [2][(size_t)BATCH * NNODE * HID];   // rna(relu(LN(out1)))
__device__ float    g_stats1[2][BATCH][2];                      // sum, sumsq of conv1 raw
__device__ float    g_stats2[2][BATCH][2];                      // sum, sumsq of conv2 raw
__device__ unsigned g_max2  [2][BATCH][HID];                    // per (b,o) max of conv2 raw (ordered)

// monotone float<->uint encoding so atomicMax(unsigned) == float max
__device__ __forceinline__ unsigned f2ord(float f) {
    unsigned u = __float_as_uint(f);
    return (u & 0x80000000u) ? ~u : (u | 0x80000000u);
}
__device__ __forceinline__ float ord2f(unsigned u) {
    return __uint_as_float((u & 0x80000000u) ? (u ^ 0x80000000u) : ~u);
}

// ---------------- small PTX helpers (all portable, sm_80+) ----------------
__device__ __forceinline__ float rna_tf32(float f) {
    uint32_t r;
    asm("cvt.rna.tf32.f32 %0, %1;" : "=r"(r) : "f"(f));
    return __uint_as_float(r);
}
__device__ __forceinline__ uint32_t smem_u32(const void* p) {
    uint32_t a;
    asm("{ .reg .u64 t; cvta.to.shared.u64 t, %1; cvt.u32.u64 %0, t; }" : "=r"(a) : "l"(p));
    return a;
}
__device__ __forceinline__ void cp_async16(uint32_t dst, const float* src) {
    asm volatile("cp.async.cg.shared.global [%0], [%1], 16;" :: "r"(dst), "l"(src));
}
__device__ __forceinline__ void cp_commit() {
    asm volatile("cp.async.commit_group;" ::: "memory");
}
template<int N> __device__ __forceinline__ void cp_wait() {
    asm volatile("cp.async.wait_group %0;" :: "n"(N) : "memory");
}
// D += A(16x8) * B(8x8), tf32 inputs (values already RNA-rounded), fp32 accum
__device__ __forceinline__ void mma_tf32(float* d, const float4& a, float b0, float b1) {
    asm volatile(
        "mma.sync.aligned.m16n8k8.row.col.f32.tf32.tf32.f32 "
        "{%0,%1,%2,%3}, {%4,%5,%6,%7}, {%8,%9}, {%0,%1,%2,%3};\n"
        : "+f"(d[0]), "+f"(d[1]), "+f"(d[2]), "+f"(d[3])
        : "r"(__float_as_uint(a.x)), "r"(__float_as_uint(a.y)),
          "r"(__float_as_uint(a.z)), "r"(__float_as_uint(a.w)),
          "r"(__float_as_uint(b0)), "r"(__float_as_uint(b1)));
}

// ---------------- init: zero stats, node-0 rows, max buffers ----------------
__global__ void init_kernel() {
    int i = blockIdx.x * blockDim.x + threadIdx.x;
    if (i < 2 * BATCH * HID) {
        int e = i / (BATCH * HID);
        int r = i % (BATCH * HID);
        int b = r / HID, o = r % HID;
        g_max2[e][b][o] = 0x80000000u;                       // encodes 0.0f (null node contributes 0)
        g_out1[e][(size_t)b * NNODE * HID + o] = 0.0f;       // zero null-node row
    }
    if (i < 2 * BATCH) {
        int e = i / BATCH, b = i % BATCH;
        g_stats1[e][b][0] = 0.f; g_stats1[e][b][1] = 0.f;
        g_stats2[e][b][0] = 0.f; g_stats2[e][b][1] = 0.f;
    }
}

// ---------------- transpose (B,C,N) -> (B,N,C), rounding to tf32 -------------
__global__ void transpose_kernel(const float* __restrict__ lf, const float* __restrict__ pf) {
    __shared__ float tile[32][33];
    int e = blockIdx.z >> 6;
    int b = blockIdx.z & 63;
    const float* src = e ? pf : lf;
    int n0 = blockIdx.x << 5, c0 = blockIdx.y << 5;
    int tx = threadIdx.x, ty = threadIdx.y;
#pragma unroll
    for (int i = 0; i < 32; i += 8) {
        int n = n0 + tx;
        if (n < NNODE) tile[ty + i][tx] = src[((size_t)b * CIN + c0 + ty + i) * NNODE + n];
    }
    __syncthreads();
#pragma unroll
    for (int i = 0; i < 32; i += 8) {
        int n = n0 + ty + i;
        if (n < NNODE)
            g_featsT[e][((size_t)b * NNODE + n) * CIN + c0 + tx] = rna_tf32(tile[tx][ty + i]);
    }
}

// ---------------- transform: g_h = rna(relu(LN1(g_out1))) ----------------
__global__ void transform_kernel() {
    const int P4 = NNODE * HID / 4;            // 131104 float4 per (e,b)
    int i = blockIdx.x * blockDim.x + threadIdx.x;
    if (i >= P4) return;
    int e = blockIdx.y >> 6, b = blockIdx.y & 63;
    float st = g_stats1[e][b][0], sst = g_stats1[e][b][1];
    const float cnt = (float)(HID * NNODE);
    float mean = st / cnt;
    float var = (sst - st * st / cnt) / (cnt - 1.f);
    float inv = 1.f / (sqrtf(var) + EPSV);
    float4 x = ((const float4*)(g_out1[e] + (size_t)b * NNODE * HID))[i];
    float4 y;
    y.x = rna_tf32(fmaxf(0.f, (x.x - mean) * inv));
    y.y = rna_tf32(fmaxf(0.f, (x.y - mean) * inv));
    y.z = rna_tf32(fmaxf(0.f, (x.z - mean) * inv));
    y.w = rna_tf32(fmaxf(0.f, (x.w - mean) * inv));
    ((float4*)(g_h[e] + (size_t)b * NNODE * HID))[i] = y;
}

// =================================================================================
// Warp-MMA tree conv: D[64(mh), 32nodes] = W * G^T via mma.sync m16n8k8 tf32.
// Grid (148, mh=2, e=2); CTA 128 thr = 4 warps (2m x 2n), warp tile M=32 x N=16.
// W fragment-packed in smem (LDS.128); G double-buffered, filled by cp.async
// (sources pre-rounded to tf32 bits: g_featsT / g_h).
// SECOND=false: store raw out1 + stats1.  SECOND=true: stats2 + per-(b,o) max.
// =================================================================================
template<int KD, bool SECOND>
__global__ void __launch_bounds__(128, SECOND ? 1 : 2) conv_mma_kernel(
    const int* __restrict__ children,
    const float* __restrict__ Wl, const float* __restrict__ bl,
    const float* __restrict__ Wp, const float* __restrict__ bp)
{
    constexpr int NT   = 32;              // nodes per tile
    constexpr int CPC  = KD / 3;          // floats per child slot (64 / 128)
    constexpr int KDP  = KD + 4;          // padded G row stride (floats)
    constexpr int NCH  = KD / 8;          // k-chunks
    constexpr int UNITS = CPC / 4;        // 16B units per child row (16 / 32)
    constexpr int TPB  = TNODE / NT;      // 128 tiles per example
    constexpr int TILES = BATCH * TPB;    // 8192 per (e, mh)
    constexpr int GCNT = NT * KDP;        // floats per G buffer

    const int e  = blockIdx.z;
    const int mh = blockIdx.y;
    const int per = (TILES + 147) / 148;
    const int t0 = blockIdx.x * per;
    const int t1 = min(TILES, t0 + per);
    if (t0 >= t1) return;

    extern __shared__ float smem[];
    float* s_W    = smem;                 // 64*KD floats, fragment-packed
    float* s_G    = smem + 64 * KD;       // 2 * GCNT
    float* s_bias = s_G + 2 * GCNT;       // 64
    const uint32_t g_u32 = smem_u32(s_G);

    const int tid = threadIdx.x;
    const int wid = tid >> 5, l = tid & 31;
    const int mp = wid >> 1, np = wid & 1;

    // ---- fill W fragment-packed (pre-rounded tf32) + bias ----
    const float* Wg = e ? Wp : Wl;
    const float* bg = e ? bp : bl;
    for (int idx = tid; idx < 64 * KD; idx += 128) {
        int reg  = idx & 3;
        int lane = (idx >> 2) & 31;
        int rest = idx >> 7;
        int mt   = rest & 1;
        int q    = (rest >> 1) % NCH;
        int mpp  = (rest >> 1) / NCH;
        int m_loc = mpp * 32 + mt * 16 + (lane >> 2) + ((reg & 1) << 3);
        int k     = q * 8 + (lane & 3) + ((reg >> 1) << 2);
        int c = k % CPC, k3 = k / CPC;
        s_W[idx] = rna_tf32(Wg[(size_t)(mh * 64 + m_loc) * KD + c * 3 + k3]);
    }
    if (tid < 64) s_bias[tid] = bg[mh * 64 + tid];

    // ---- gather issue: raw cp.async of pre-transformed rows ----
    auto issue_gather = [&](int t, int buf) {
        int b = t >> 7;                       // / TPB
        int tl = t & 127;
        const int* chb = children + (size_t)b * 3 * TNODE + 3 * tl * NT;
        const float* sb = SECOND ? g_h[e] + (size_t)b * NNODE * HID
                                 : g_featsT[e] + (size_t)b * NNODE * CIN;
        uint32_t gd = g_u32 + (uint32_t)buf * (GCNT * 4);
#pragma unroll
        for (int idx = tid; idx < 3 * NT * UNITS; idx += 128) {
            int row = idx / UNITS;
            int u   = idx & (UNITS - 1);
            int i = row / 3, k3 = row - i * 3;
            int child = __ldg(chb + row);
            cp_async16(gd + (uint32_t)(i * KDP + k3 * CPC + u * 4) * 4,
                       sb + (size_t)child * CPC + u * 4);
        }
        cp_commit();
    };

    issue_gather(t0, 0);
    if (t0 + 1 < t1) issue_gather(t0 + 1, 1);

    for (int t = t0; t < t1; ++t) {
        int buf = (t - t0) & 1;
        if (t + 1 < t1) cp_wait<1>(); else cp_wait<0>();
        __syncthreads();

        // ---- MMA: warp tile M=32 x N=16, K=KD ----
        float d[2][2][4];
#pragma unroll
        for (int mt = 0; mt < 2; ++mt)
#pragma unroll
            for (int nt = 0; nt < 2; ++nt)
#pragma unroll
                for (int r = 0; r < 4; ++r) d[mt][nt][r] = 0.f;

        const float* Gb = s_G + buf * GCNT;
        const int nrow0 = np * 16 + (l >> 2);
        const int kcol  = l & 3;
#pragma unroll 4
        for (int q = 0; q < NCH; ++q) {
            float4 a0 = ((const float4*)(s_W + (((mp * NCH + q) * 2 + 0) << 7)))[l];
            float4 a1 = ((const float4*)(s_W + (((mp * NCH + q) * 2 + 1) << 7)))[l];
            const float* gp0 = Gb + (size_t)(nrow0    ) * KDP + q * 8 + kcol;
            const float* gp1 = Gb + (size_t)(nrow0 + 8) * KDP + q * 8 + kcol;
            float b00 = gp0[0], b01 = gp0[4];
            float b10 = gp1[0], b11 = gp1[4];
            mma_tf32(d[0][0], a0, b00, b01);
            mma_tf32(d[0][1], a0, b10, b11);
            mma_tf32(d[1][0], a1, b00, b01);
            mma_tf32(d[1][1], a1, b10, b11);
        }

        // ---- epilogue ----
        int b = t >> 7, tl = t & 127;
        int n0 = 1 + tl * NT;
        float bb[2][2];
#pragma unroll
        for (int mt = 0; mt < 2; ++mt)
#pragma unroll
            for (int h = 0; h < 2; ++h)
                bb[mt][h] = s_bias[mp * 32 + mt * 16 + (l >> 2) + h * 8];

        float ls = 0.f, lss = 0.f;
        if (SECOND) {
            float mx[2][2] = {{-3.4e38f, -3.4e38f}, {-3.4e38f, -3.4e38f}};
#pragma unroll
            for (int mt = 0; mt < 2; ++mt)
#pragma unroll
                for (int nt = 0; nt < 2; ++nt)
#pragma unroll
                    for (int r = 0; r < 4; ++r) {
                        float v = d[mt][nt][r] + bb[mt][r >> 1];
                        ls += v; lss += v * v;
                        mx[mt][r >> 1] = fmaxf(mx[mt][r >> 1], v);
                    }
#pragma unroll
            for (int mt = 0; mt < 2; ++mt)
#pragma unroll
                for (int h = 0; h < 2; ++h) {
                    float m = mx[mt][h];
                    m = fmaxf(m, __shfl_xor_sync(0xffffffffu, m, 1));
                    m = fmaxf(m, __shfl_xor_sync(0xffffffffu, m, 2));
                    if ((l & 3) == 0) {
                        int mg = mh * 64 + mp * 32 + mt * 16 + (l >> 2) + h * 8;
                        atomicMax(&g_max2[e][b][mg], f2ord(m));
                    }
                }
        } else {
            float* ob = g_out1[e] + ((size_t)b * NNODE + n0) * HID + mh * 64;
#pragma unroll
            for (int mt = 0; mt < 2; ++mt)
#pragma unroll
                for (int nt = 0; nt < 2; ++nt)
#pragma unroll
                    for (int r = 0; r < 4; ++r) {
                        float v = d[mt][nt][r] + bb[mt][r >> 1];
                        int n_loc = np * 16 + nt * 8 + (l & 3) * 2 + (r & 1);
                        int m_loc = mp * 32 + mt * 16 + (l >> 2) + (r >> 1) * 8;
                        ob[(size_t)n_loc * HID + m_loc] = v;
                        ls += v; lss += v * v;
                    }
        }
#pragma unroll
        for (int off = 16; off; off >>= 1) {
            ls  += __shfl_xor_sync(0xffffffffu, ls, off);
            lss += __shfl_xor_sync(0xffffffffu, lss, off);
        }
        if (l == 0) {
            float* st = SECOND ? g_stats2[e][b] : g_stats1[e][b];
            atomicAdd(&st[0], ls);
            atomicAdd(&st[1], lss);
        }

        __syncthreads();                      // all warps done reading this buffer
        if (t + 2 < t1) issue_gather(t + 2, buf);
    }
}

// ---------------- finalize: LN2+relu on max, concat, mu/logvar GEMVs ---------------
__global__ void finalize_kernel(const float* __restrict__ Wmu, const float* __restrict__ bmu,
                                const float* __restrict__ Wlv, const float* __restrict__ blv,
                                float* __restrict__ out)
{
    __shared__ float comb[2 * HID];
    int b = blockIdx.x, tid = threadIdx.x;
    const float cntv = (float)(HID * NNODE);
#pragma unroll
    for (int e = 0; e < 2; ++e) {
        float st  = g_stats2[e][b][0];
        float sst = g_stats2[e][b][1];
        float mean = st / cntv;
        float var  = (sst - st * st / cntv) / (cntv - 1.f);
        float inv  = 1.f / (sqrtf(var) + EPSV);
        if (tid < HID) {
            float m = ord2f(g_max2[e][b][tid]);
            comb[e * HID + tid] = fmaxf(0.f, (m - mean) * inv);
        }
    }
    __syncthreads();
    if (tid < 64) {
        float acc = bmu[tid];
        for (int j = 0; j < 2 * HID; ++j) acc += Wmu[tid * 2 * HID + j] * comb[j];
        out[b * LAT + tid] = acc;
    } else if (tid < 128) {
        int t = tid - 64;
        float acc = blv[t];
        for (int j = 0; j < 2 * HID; ++j) acc += Wlv[t * 2 * HID + j] * comb[j];
        out[BATCH * LAT + b * LAT + t] = acc;
    }
}

// -------------------------------- launch --------------------------------
extern "C" void kernel_launch(void* const* d_in, const int* in_sizes, int n_in,
                              void* d_out, int out_size)
{
    const float* lf  = (const float*)d_in[0];
    const float* pf  = (const float*)d_in[1];
    const int*   ch  = (const int*)d_in[2];
    const float* Wl1 = (const float*)d_in[3];  const float* bl1 = (const float*)d_in[4];
    const float* Wl2 = (const float*)d_in[5];  const float* bl2 = (const float*)d_in[6];
    const float* Wp1 = (const float*)d_in[7];  const float* bp1 = (const float*)d_in[8];
    const float* Wp2 = (const float*)d_in[9];  const float* bp2 = (const float*)d_in[10];
    const float* Wmu = (const float*)d_in[11]; const float* bmu = (const float*)d_in[12];
    const float* Wlv = (const float*)d_in[13]; const float* blv = (const float*)d_in[14];
    float* out = (float*)d_out;

    // dynamic smem: W(64*KD) + 2 G buffers (NT*(KD+4)) + bias(64)
    const int SMEM1 = (64 * 192 + 2 * 32 * 196 + 64) * 4;   //  99,584 B (2 CTAs/SM)
    const int SMEM2 = (64 * 384 + 2 * 32 * 388 + 64) * 4;   // 197,888 B (1 CTA/SM)
    cudaFuncSetAttribute(conv_mma_kernel<192, false>,
                         cudaFuncAttributeMaxDynamicSharedMemorySize, SMEM1);
    cudaFuncSetAttribute(conv_mma_kernel<384, true>,
                         cudaFuncAttributeMaxDynamicSharedMemorySize, SMEM2);

    init_kernel<<<(2 * BATCH * HID + 255) / 256, 256>>>();
    transpose_kernel<<<dim3((NNODE + 31) / 32, CIN / 32, 2 * BATCH), dim3(32, 8)>>>(lf, pf);
    conv_mma_kernel<192, false><<<dim3(148, 2, 2), 128, SMEM1>>>(ch, Wl1, bl1, Wp1, bp1);
    transform_kernel<<<dim3((NNODE * HID / 4 + 255) / 256, 2 * BATCH), 256>>>();
    conv_mma_kernel<384, true ><<<dim3(148, 2, 2), 128, SMEM2>>>(ch, Wl2, bl2, Wp2, bp2);
    finalize_kernel<<<BATCH, 128>>>(Wmu, bmu, Wlv, blv, out);
}